// round 13
// baseline (speedup 1.0000x reference)
#include <cuda_runtime.h>
#include <cuda_fp16.h>
#include <math.h>
#include <stdint.h>

#define D_DIM 512
#define MAX_N 65536
#define MAX_C 1024

// Scratch (allocation-free rule). Referenced ONLY from device code.
__device__ float g_inv[MAX_N];
__device__ float g_sums[MAX_C * D_DIM];
__device__ float g_cnt[MAX_C];
__device__ float g_protos[MAX_C * D_DIM];
__device__ int   g_lab64;
// Precomputed fp16 operands for the tensor-core GEMM
__device__ __half g_Ah[MAX_N * D_DIM];   // 64 MB
__device__ __half g_Bh[MAX_C * D_DIM];   // 1 MB

// ---------------------------------------------------------------------------
__device__ __forceinline__ uint32_t smem_u32(const void* p) {
    uint32_t a;
    asm("{ .reg .u64 t; cvta.to.shared.u64 t, %1; cvt.u32.u64 %0, t; }"
        : "=r"(a) : "l"(p));
    return a;
}
__device__ __forceinline__ uint32_t sw128(uint32_t off) { return off ^ ((off >> 3) & 0x70); }
__device__ __forceinline__ uint32_t h2u(__half2 v) {
    return *reinterpret_cast<uint32_t*>(&v);
}
__device__ __forceinline__ void ldsm_x4(uint32_t& r0, uint32_t& r1, uint32_t& r2,
                                        uint32_t& r3, uint32_t addr) {
    asm volatile("ldmatrix.sync.aligned.m8n8.x4.shared.b16 {%0,%1,%2,%3}, [%4];"
                 : "=r"(r0), "=r"(r1), "=r"(r2), "=r"(r3) : "r"(addr));
}
__device__ __forceinline__ void mma_f16(float* c, const uint32_t* a,
                                        uint32_t b0, uint32_t b1) {
    asm volatile(
        "mma.sync.aligned.m16n8k16.row.col.f32.f16.f16.f32 "
        "{%0,%1,%2,%3}, {%4,%5,%6,%7}, {%8,%9}, {%0,%1,%2,%3};"
        : "+f"(c[0]), "+f"(c[1]), "+f"(c[2]), "+f"(c[3])
        : "r"(a[0]), "r"(a[1]), "r"(a[2]), "r"(a[3]), "r"(b0), "r"(b1));
}
__device__ __forceinline__ void cp16(uint32_t dst, const void* src) {
    asm volatile("cp.async.cg.shared.global [%0], [%1], 16;"
                 :: "r"(dst), "l"(src) : "memory");
}
__device__ __forceinline__ void cp_commit() {
    asm volatile("cp.async.commit_group;" ::: "memory");
}
template <int N>
__device__ __forceinline__ void cp_wait() {
    asm volatile("cp.async.wait_group %0;" :: "n"(N) : "memory");
}
__device__ __forceinline__ void stg_cs_v2(float* p, float x, float y) {
    asm volatile("st.global.cs.v2.f32 [%0], {%1, %2};"
                 :: "l"(p), "f"(x), "f"(y) : "memory");
}

// ===========================================================================
// zero + label-dtype detect (fused)
// ===========================================================================
__global__ void zero_detect(const int* __restrict__ words, int n_words) {
    int i = blockIdx.x * blockDim.x + threadIdx.x;
    if (i < MAX_C * D_DIM) g_sums[i] = 0.0f;
    if (i < MAX_C)         g_cnt[i]  = 0.0f;
    if (i == 0) {
        int all_zero = 1;
        for (int k = 1; k < 256 && k < n_words; k += 2)
            if (words[k] != 0) { all_zero = 0; break; }
        g_lab64 = all_zero;
    }
}

// ===========================================================================
// Per-row L2 norm + segment scatter + emit fp16 of normalized feats
// ===========================================================================
__global__ void __launch_bounds__(128) normalize_scatter(
    const float* __restrict__ feats, const void* __restrict__ labels, int Ccls)
{
    const int row = blockIdx.x;
    const int t   = threadIdx.x;

    const float4 v = reinterpret_cast<const float4*>(feats + (size_t)row * D_DIM)[t];
    float ss = v.x * v.x + v.y * v.y + v.z * v.z + v.w * v.w;
    #pragma unroll
    for (int o = 16; o > 0; o >>= 1) ss += __shfl_xor_sync(0xffffffffu, ss, o);
    __shared__ float warp_ss[4];
    if ((t & 31) == 0) warp_ss[t >> 5] = ss;
    __syncthreads();
    const float tot = warp_ss[0] + warp_ss[1] + warp_ss[2] + warp_ss[3];
    const float inv = 1.0f / fmaxf(sqrtf(tot), 1e-12f);
    if (t == 0) g_inv[row] = inv;

    float4 f = make_float4(v.x * inv, v.y * inv, v.z * inv, v.w * inv);

    __half2 a0 = __float22half2_rn(make_float2(f.x, f.y));
    __half2 a1 = __float22half2_rn(make_float2(f.z, f.w));
    const size_t e = (size_t)row * D_DIM + t * 4;
    *reinterpret_cast<uint2*>(reinterpret_cast<char*>(g_Ah) + e * 2) =
        make_uint2(h2u(a0), h2u(a1));

    int lab;
    if (g_lab64) lab = (int)reinterpret_cast<const long long*>(labels)[row];
    else         lab = reinterpret_cast<const int*>(labels)[row];
    if (lab < 0) lab = 0;
    if (lab >= Ccls) lab = Ccls - 1;

    float* s = g_sums + (size_t)lab * D_DIM + t * 4;
    asm volatile("red.global.add.v4.f32 [%0], {%1, %2, %3, %4};"
                 :: "l"(s), "f"(f.x), "f"(f.y), "f"(f.z), "f"(f.w) : "memory");
    if (t == 0) atomicAdd(&g_cnt[lab], 1.0f);
}

// ===========================================================================
// Prototype EMA + renorm + emit fp16 of the updated bank
// ===========================================================================
__global__ void __launch_bounds__(128) proto_update(const float* __restrict__ protos)
{
    const int c = blockIdx.x;
    const int t = threadIdx.x;
    const float cnt   = g_cnt[c];
    const float denom = fmaxf(cnt, 1.0f);

    const float4 p = reinterpret_cast<const float4*>(protos + (size_t)c * D_DIM)[t];
    const float4 s = reinterpret_cast<const float4*>(g_sums  + (size_t)c * D_DIM)[t];

    float4 m;
    m.x = 0.9f * p.x + 0.1f * (s.x / denom);
    m.y = 0.9f * p.y + 0.1f * (s.y / denom);
    m.z = 0.9f * p.z + 0.1f * (s.z / denom);
    m.w = 0.9f * p.w + 0.1f * (s.w / denom);

    float ss = m.x * m.x + m.y * m.y + m.z * m.z + m.w * m.w;
    #pragma unroll
    for (int o = 16; o > 0; o >>= 1) ss += __shfl_xor_sync(0xffffffffu, ss, o);
    __shared__ float warp_ss[4];
    if ((t & 31) == 0) warp_ss[t >> 5] = ss;
    __syncthreads();
    const float tot = warp_ss[0] + warp_ss[1] + warp_ss[2] + warp_ss[3];
    const float inv = 1.0f / fmaxf(sqrtf(tot), 1e-12f);

    float4 o4;
    if (cnt > 0.0f) {
        o4.x = m.x * inv; o4.y = m.y * inv; o4.z = m.z * inv; o4.w = m.w * inv;
    } else {
        o4 = p;
    }
    reinterpret_cast<float4*>(g_protos + (size_t)c * D_DIM)[t] = o4;

    __half2 b0 = __float22half2_rn(make_float2(o4.x, o4.y));
    __half2 b1 = __float22half2_rn(make_float2(o4.z, o4.w));
    const size_t e = (size_t)c * D_DIM + t * 4;
    *reinterpret_cast<uint2*>(reinterpret_cast<char*>(g_Bh) + e * 2) =
        make_uint2(h2u(b0), h2u(b1));
}

// ===========================================================================
// GEMM: sim = Ah @ Bh^T, fp16. Block 128x128, 128 threads, 4 warps (2x2),
// warp tile 64x64 (128 B/mma vs 192 at 32x64). 2-stage cp.async (64KB/CTA)
// -> 3 CTAs/SM = 12 warps/SM, decorrelated. 170-reg cap; JIT fragments
// (ah 16 + bh 4 live) keep footprint ~165.
// ===========================================================================
#define GBM 128
#define GBN 128
#define KCH 64
#define NCHUNK (D_DIM / KCH)                 // 8
#define TILE_A 16384                         // 128x64 fp16
#define STAGE_B (2 * TILE_A)                 // A + B = 32KB
#define NSTAGE 2
#define SMEM_TOTAL (NSTAGE * STAGE_B)        // 65536 per CTA; 3/SM = 192KB

__global__ void __launch_bounds__(128, 3) gemm_mma(
    float* __restrict__ Cmat, int Ccls)
{
    extern __shared__ char smem[];
    const uint32_t sbase = smem_u32(smem);

    const int tid = threadIdx.x;
    const int wid = tid >> 5, l = tid & 31;
    const int wy = wid >> 1, wx = wid & 1;          // 2x2 warps, 64x64 tiles
    const int bm = blockIdx.y * GBM, bn = blockIdx.x * GBN;

    // ---- cp.async fill mapping: q = 16B segment, r0 = base row (0..15) ----
    // Rows r0+16s; sw128 is linear in +16-row (=+2048B) steps.
    const int q = tid & 7;
    const int r0 = tid >> 3;
    const uint32_t d0 = sw128((uint32_t)(r0 * 128 + q * 16));
    const char* srcA = reinterpret_cast<const char*>(g_Ah)
                     + ((size_t)(bm + r0) * D_DIM + q * 8) * 2;
    const char* srcB = reinterpret_cast<const char*>(g_Bh)
                     + ((size_t)(bn + r0) * D_DIM + q * 8) * 2;

    auto issue_stage = [&](int c) {
        const uint32_t st = sbase + (uint32_t)(c & 1) * STAGE_B;
        const int koff = c * KCH * 2;
        #pragma unroll
        for (int s = 0; s < 8; s++)
            cp16(st + d0 + s * 2048, srcA + (size_t)s * 16 * (D_DIM * 2) + koff);
        #pragma unroll
        for (int s = 0; s < 8; s++)
            cp16(st + TILE_A + d0 + s * 2048, srcB + (size_t)s * 16 * (D_DIM * 2) + koff);
        cp_commit();
    };

    // ---- ldmatrix lane addressing (validated R5-R12) ----
    const int a_row = (l & 15);
    const int a_kh  = (l >> 4);
    const int b_row = (l & 7) + (l >> 4) * 8;
    const int b_kh  = (l >> 3) & 1;

    float acc[4][8][4];
    #pragma unroll
    for (int m = 0; m < 4; m++)
        #pragma unroll
        for (int n = 0; n < 8; n++)
            #pragma unroll
            for (int i = 0; i < 4; i++) acc[m][n][i] = 0.0f;

    issue_stage(0);

    for (int c = 0; c < NCHUNK; c++) {
        cp_wait<0>();          // fill c complete
        __syncthreads();       // buffer (c+1)&1 fully consumed (iter c-1)
        if (c + 1 < NCHUNK) issue_stage(c + 1);

        const uint32_t ah_b = sbase + (uint32_t)(c & 1) * STAGE_B;
        const uint32_t bh_b = ah_b + TILE_A;

        #pragma unroll
        for (int ks = 0; ks < 4; ks++) {
            // A fragments resident for the ks step (reused 4x each)
            uint32_t ah[4][4];
            #pragma unroll
            for (int mb = 0; mb < 4; mb++) {
                const uint32_t off = sw128((uint32_t)(
                    (wy * 64 + mb * 16 + a_row) * 128 + ks * 32 + a_kh * 16));
                ldsm_x4(ah[mb][0], ah[mb][1], ah[mb][2], ah[mb][3], ah_b + off);
            }
            // B fragments just-in-time (4-reg liveness)
            #pragma unroll
            for (int nb2 = 0; nb2 < 4; nb2++) {
                uint32_t bh[4];
                const uint32_t off = sw128((uint32_t)(
                    (wx * 64 + nb2 * 16 + b_row) * 128 + ks * 32 + b_kh * 16));
                ldsm_x4(bh[0], bh[1], bh[2], bh[3], bh_b + off);
                #pragma unroll
                for (int mb = 0; mb < 4; mb++)
                    #pragma unroll
                    for (int h = 0; h < 2; h++)
                        mma_f16(acc[mb][nb2 * 2 + h], ah[mb],
                                bh[h * 2], bh[h * 2 + 1]);
            }
        }
    }

    // ---- epilogue (streaming stores) ----
    #pragma unroll
    for (int mb = 0; mb < 4; mb++) {
        const int row = bm + wy * 64 + mb * 16 + (l >> 2);
        #pragma unroll
        for (int nb = 0; nb < 8; nb++) {
            const int col = bn + wx * 64 + nb * 8 + (l & 3) * 2;
            float* o0 = Cmat + (size_t)row * Ccls + col;
            float* o1 = o0 + (size_t)8 * Ccls;
            stg_cs_v2(o0, acc[mb][nb][0], acc[mb][nb][1]);
            stg_cs_v2(o1, acc[mb][nb][2], acc[mb][nb][3]);
        }
    }
}

// ---------------------------------------------------------------------------
extern "C" void kernel_launch(void* const* d_in, const int* in_sizes, int n_in,
                              void* d_out, int out_size)
{
    int i_feats = 0, i_protos = 0, i_labels = 0;
    for (int i = 1; i < n_in; i++) {
        if (in_sizes[i] > in_sizes[i_feats])  i_feats  = i;
        if (in_sizes[i] < in_sizes[i_labels]) i_labels = i;
    }
    for (int i = 0; i < n_in; i++)
        if (i != i_feats && i != i_labels) i_protos = i;

    const float* feats  = (const float*)d_in[i_feats];
    const float* protos = (const float*)d_in[i_protos];
    const void*  labels = d_in[i_labels];

    const int N = in_sizes[i_labels];
    const int C = in_sizes[i_protos] / D_DIM;
    float* out = (float*)d_out;

    {
        int total = MAX_C * D_DIM;
        zero_detect<<<(total + 255) / 256, 256>>>((const int*)labels, N);
    }
    normalize_scatter<<<N, 128>>>(feats, labels, C);
    proto_update<<<C, 128>>>(protos);

    static bool smem_set = false;
    if (!smem_set) {
        cudaFuncSetAttribute(gemm_mma, cudaFuncAttributeMaxDynamicSharedMemorySize,
                             SMEM_TOTAL);
        smem_set = true;
    }
    dim3 grid(C / GBN, N / GBM);   // (8, 512) = 4096 CTAs
    gemm_mma<<<grid, 128, SMEM_TOTAL>>>(out, C);
}

// round 15
// speedup vs baseline: 1.0689x; 1.0689x over previous
#include <cuda_runtime.h>
#include <cuda_fp16.h>
#include <math.h>
#include <stdint.h>

#define D_DIM 512
#define MAX_N 65536
#define MAX_C 1024

// Scratch (allocation-free rule). Referenced ONLY from device code.
__device__ float g_inv[MAX_N];
__device__ float g_sums[MAX_C * D_DIM];
__device__ float g_cnt[MAX_C];
__device__ float g_protos[MAX_C * D_DIM];
__device__ int   g_lab64;
// Precomputed fp16 operands for the tensor-core GEMM
__device__ __half g_Ah[MAX_N * D_DIM];   // 64 MB
__device__ __half g_Bh[MAX_C * D_DIM];   // 1 MB

// ---------------------------------------------------------------------------
__device__ __forceinline__ uint32_t smem_u32(const void* p) {
    uint32_t a;
    asm("{ .reg .u64 t; cvta.to.shared.u64 t, %1; cvt.u32.u64 %0, t; }"
        : "=r"(a) : "l"(p));
    return a;
}
__device__ __forceinline__ uint32_t sw128(uint32_t off) { return off ^ ((off >> 3) & 0x70); }
__device__ __forceinline__ uint32_t h2u(__half2 v) {
    return *reinterpret_cast<uint32_t*>(&v);
}
__device__ __forceinline__ void ldsm_x4(uint32_t& r0, uint32_t& r1, uint32_t& r2,
                                        uint32_t& r3, uint32_t addr) {
    asm volatile("ldmatrix.sync.aligned.m8n8.x4.shared.b16 {%0,%1,%2,%3}, [%4];"
                 : "=r"(r0), "=r"(r1), "=r"(r2), "=r"(r3) : "r"(addr));
}
__device__ __forceinline__ void mma_f16(float* c, const uint32_t* a,
                                        uint32_t b0, uint32_t b1) {
    asm volatile(
        "mma.sync.aligned.m16n8k16.row.col.f32.f16.f16.f32 "
        "{%0,%1,%2,%3}, {%4,%5,%6,%7}, {%8,%9}, {%0,%1,%2,%3};"
        : "+f"(c[0]), "+f"(c[1]), "+f"(c[2]), "+f"(c[3])
        : "r"(a[0]), "r"(a[1]), "r"(a[2]), "r"(a[3]), "r"(b0), "r"(b1));
}
__device__ __forceinline__ void cp16(uint32_t dst, const void* src) {
    asm volatile("cp.async.cg.shared.global [%0], [%1], 16;"
                 :: "r"(dst), "l"(src) : "memory");
}
__device__ __forceinline__ void cp_commit() {
    asm volatile("cp.async.commit_group;" ::: "memory");
}
template <int N>
__device__ __forceinline__ void cp_wait() {
    asm volatile("cp.async.wait_group %0;" :: "n"(N) : "memory");
}
__device__ __forceinline__ void stg_cs_v2(float* p, float x, float y) {
    asm volatile("st.global.cs.v2.f32 [%0], {%1, %2};"
                 :: "l"(p), "f"(x), "f"(y) : "memory");
}

// ===========================================================================
// zero + label-dtype detect (fused)
// ===========================================================================
__global__ void zero_detect(const int* __restrict__ words, int n_words) {
    int i = blockIdx.x * blockDim.x + threadIdx.x;
    if (i < MAX_C * D_DIM) g_sums[i] = 0.0f;
    if (i < MAX_C)         g_cnt[i]  = 0.0f;
    if (i == 0) {
        int all_zero = 1;
        for (int k = 1; k < 256 && k < n_words; k += 2)
            if (words[k] != 0) { all_zero = 0; break; }
        g_lab64 = all_zero;
    }
}

// ===========================================================================
// Per-row L2 norm + segment scatter + emit fp16 of normalized feats
// ===========================================================================
__global__ void __launch_bounds__(128) normalize_scatter(
    const float* __restrict__ feats, const void* __restrict__ labels, int Ccls)
{
    const int row = blockIdx.x;
    const int t   = threadIdx.x;

    const float4 v = reinterpret_cast<const float4*>(feats + (size_t)row * D_DIM)[t];
    float ss = v.x * v.x + v.y * v.y + v.z * v.z + v.w * v.w;
    #pragma unroll
    for (int o = 16; o > 0; o >>= 1) ss += __shfl_xor_sync(0xffffffffu, ss, o);
    __shared__ float warp_ss[4];
    if ((t & 31) == 0) warp_ss[t >> 5] = ss;
    __syncthreads();
    const float tot = warp_ss[0] + warp_ss[1] + warp_ss[2] + warp_ss[3];
    const float inv = 1.0f / fmaxf(sqrtf(tot), 1e-12f);
    if (t == 0) g_inv[row] = inv;

    float4 f = make_float4(v.x * inv, v.y * inv, v.z * inv, v.w * inv);

    __half2 a0 = __float22half2_rn(make_float2(f.x, f.y));
    __half2 a1 = __float22half2_rn(make_float2(f.z, f.w));
    const size_t e = (size_t)row * D_DIM + t * 4;
    *reinterpret_cast<uint2*>(reinterpret_cast<char*>(g_Ah) + e * 2) =
        make_uint2(h2u(a0), h2u(a1));

    int lab;
    if (g_lab64) lab = (int)reinterpret_cast<const long long*>(labels)[row];
    else         lab = reinterpret_cast<const int*>(labels)[row];
    if (lab < 0) lab = 0;
    if (lab >= Ccls) lab = Ccls - 1;

    float* s = g_sums + (size_t)lab * D_DIM + t * 4;
    asm volatile("red.global.add.v4.f32 [%0], {%1, %2, %3, %4};"
                 :: "l"(s), "f"(f.x), "f"(f.y), "f"(f.z), "f"(f.w) : "memory");
    if (t == 0) atomicAdd(&g_cnt[lab], 1.0f);
}

// ===========================================================================
// Prototype EMA + renorm + emit fp16 of the updated bank
// ===========================================================================
__global__ void __launch_bounds__(128) proto_update(const float* __restrict__ protos)
{
    const int c = blockIdx.x;
    const int t = threadIdx.x;
    const float cnt   = g_cnt[c];
    const float denom = fmaxf(cnt, 1.0f);

    const float4 p = reinterpret_cast<const float4*>(protos + (size_t)c * D_DIM)[t];
    const float4 s = reinterpret_cast<const float4*>(g_sums  + (size_t)c * D_DIM)[t];

    float4 m;
    m.x = 0.9f * p.x + 0.1f * (s.x / denom);
    m.y = 0.9f * p.y + 0.1f * (s.y / denom);
    m.z = 0.9f * p.z + 0.1f * (s.z / denom);
    m.w = 0.9f * p.w + 0.1f * (s.w / denom);

    float ss = m.x * m.x + m.y * m.y + m.z * m.z + m.w * m.w;
    #pragma unroll
    for (int o = 16; o > 0; o >>= 1) ss += __shfl_xor_sync(0xffffffffu, ss, o);
    __shared__ float warp_ss[4];
    if ((t & 31) == 0) warp_ss[t >> 5] = ss;
    __syncthreads();
    const float tot = warp_ss[0] + warp_ss[1] + warp_ss[2] + warp_ss[3];
    const float inv = 1.0f / fmaxf(sqrtf(tot), 1e-12f);

    float4 o4;
    if (cnt > 0.0f) {
        o4.x = m.x * inv; o4.y = m.y * inv; o4.z = m.z * inv; o4.w = m.w * inv;
    } else {
        o4 = p;
    }
    reinterpret_cast<float4*>(g_protos + (size_t)c * D_DIM)[t] = o4;

    __half2 b0 = __float22half2_rn(make_float2(o4.x, o4.y));
    __half2 b1 = __float22half2_rn(make_float2(o4.z, o4.w));
    const size_t e = (size_t)c * D_DIM + t * 4;
    *reinterpret_cast<uint2*>(reinterpret_cast<char*>(g_Bh) + e * 2) =
        make_uint2(h2u(b0), h2u(b1));
}

// ===========================================================================
// Persistent GEMM: sim = Ah @ Bh^T, fp16. 296 CTAs (2/SM) loop over the
// 4096 (128x128) tiles via a flat chunk counter; 3-stage cp.async ring runs
// continuously across tile boundaries. R15 fix: ALWAYS-COMMIT — every
// iteration commits exactly one group (empty when no fill remains), so
// cp_wait<1> deterministically guarantees group lc complete at every lc
// (R14's tail race: at lc=nt8-1 the newest group WAS lc, allowed pending).
// ===========================================================================
#define GBM 128
#define GBN 128
#define KCH 64
#define NCHUNK (D_DIM / KCH)                 // 8 chunks per tile
#define TILE_A 16384                         // 128x64 fp16
#define STAGE_B (2 * TILE_A)                 // A + B = 32KB
#define NSTAGE 3
#define SMEM_TOTAL (NSTAGE * STAGE_B)        // 98304
#define NTILES_M 512                         // 65536/128
#define NTILES_N 8                           // 1024/128
#define NTILES (NTILES_M * NTILES_N)         // 4096
#define GRID_P 296                           // 2 CTAs x 148 SMs

__global__ void __launch_bounds__(256, 2) gemm_mma(
    float* __restrict__ Cmat, int Ccls)
{
    extern __shared__ char smem[];
    const uint32_t sbase = smem_u32(smem);

    const int tid = threadIdx.x;
    const int wid = tid >> 5, l = tid & 31;
    const int wy = wid >> 1, wx = wid & 1;          // 4x2 warps, 32x64 tiles
    const int bid = blockIdx.x;

    const int nt  = (NTILES - bid + GRID_P - 1) / GRID_P;
    const int nt8 = nt * NCHUNK;                    // flat chunk count

    // ---- per-thread fill mapping (tile-independent parts) ----
    const int q  = tid & 7;
    const int r0 = tid >> 3;
    const uint32_t d0 = sw128((uint32_t)(r0 * 128 + q * 16));
    const size_t rowoff = (size_t)r0 * D_DIM + q * 8;   // elements

    // issue fills for flat chunk lc (tile = bid + (lc>>3)*GRID_P); commits.
    auto issue_stage = [&](int lc) {
        const int tile = bid + (lc >> 3) * GRID_P;
        const int bm = (tile >> 3) * GBM;
        const int bn = (tile & 7) * GBN;
        const int kc = lc & 7;
        const char* sA = reinterpret_cast<const char*>(g_Ah)
                       + ((size_t)bm * D_DIM + rowoff + (size_t)kc * KCH) * 2;
        const char* sB = reinterpret_cast<const char*>(g_Bh)
                       + ((size_t)bn * D_DIM + rowoff + (size_t)kc * KCH) * 2;
        const uint32_t st = sbase + (uint32_t)(lc % NSTAGE) * STAGE_B;
        #pragma unroll
        for (int s = 0; s < 4; s++)
            cp16(st + d0 + s * 4096, sA + (size_t)s * 32 * (D_DIM * 2));
        #pragma unroll
        for (int s = 0; s < 4; s++)
            cp16(st + TILE_A + d0 + s * 4096, sB + (size_t)s * 32 * (D_DIM * 2));
        cp_commit();
    };

    // ---- ldmatrix lane addressing (validated R5-R13) ----
    const int a_row = (l & 15);
    const int a_kh  = (l >> 4);
    const int b_row = (l & 7) + (l >> 4) * 8;
    const int b_kh  = (l >> 3) & 1;

    uint32_t a_off[4], b_off[4];
    #pragma unroll
    for (int ks = 0; ks < 4; ks++) {
        a_off[ks] = sw128((uint32_t)((wy * 32 + a_row) * 128 + ks * 32 + a_kh * 16));
        b_off[ks] = sw128((uint32_t)((wx * 64 + b_row) * 128 + ks * 32 + b_kh * 16));
    }
    // +16 rows = +2048 bytes; swizzle linear in bit 11
    const uint32_t a_off16 = 2048;

    float acc[2][8][4];
    #pragma unroll
    for (int m = 0; m < 2; m++)
        #pragma unroll
        for (int n = 0; n < 8; n++)
            #pragma unroll
            for (int i = 0; i < 4; i++) acc[m][n][i] = 0.0f;

    issue_stage(0);          // nt8 >= 104 always
    issue_stage(1);

    for (int lc = 0; lc < nt8; lc++) {
        cp_wait<1>();        // newest = group lc+1 -> group lc complete
        __syncthreads();
        // ALWAYS commit one group so wait<1> stays deterministic at the tail
        if (lc + 2 < nt8) issue_stage(lc + 2);
        else              cp_commit();

        const uint32_t ah_b = sbase + (uint32_t)(lc % NSTAGE) * STAGE_B;
        const uint32_t bh_b = ah_b + TILE_A;

        #pragma unroll
        for (int ks = 0; ks < 4; ks++) {
            uint32_t ah[2][4];
            ldsm_x4(ah[0][0], ah[0][1], ah[0][2], ah[0][3], ah_b + a_off[ks]);
            ldsm_x4(ah[1][0], ah[1][1], ah[1][2], ah[1][3], ah_b + a_off[ks] + a_off16);
            #pragma unroll
            for (int nb2 = 0; nb2 < 4; nb2++) {
                uint32_t bh[4];
                ldsm_x4(bh[0], bh[1], bh[2], bh[3], bh_b + b_off[ks] + nb2 * 2048);
                #pragma unroll
                for (int mb = 0; mb < 2; mb++)
                    #pragma unroll
                    for (int h = 0; h < 2; h++)
                        mma_f16(acc[mb][nb2 * 2 + h], ah[mb],
                                bh[h * 2], bh[h * 2 + 1]);
            }
        }

        // ---- tile finished: epilogue overlaps next tile's in-flight fills
        if ((lc & 7) == 7) {
            const int tile = bid + (lc >> 3) * GRID_P;
            const int bm = (tile >> 3) * GBM;
            const int bn = (tile & 7) * GBN;
            #pragma unroll
            for (int mb = 0; mb < 2; mb++) {
                const int row = bm + wy * 32 + mb * 16 + (l >> 2);
                #pragma unroll
                for (int nb = 0; nb < 8; nb++) {
                    const int col = bn + wx * 64 + nb * 8 + (l & 3) * 2;
                    float* o0 = Cmat + (size_t)row * Ccls + col;
                    float* o1 = o0 + (size_t)8 * Ccls;
                    stg_cs_v2(o0, acc[mb][nb][0], acc[mb][nb][1]);
                    stg_cs_v2(o1, acc[mb][nb][2], acc[mb][nb][3]);
                    acc[mb][nb][0] = 0.0f; acc[mb][nb][1] = 0.0f;
                    acc[mb][nb][2] = 0.0f; acc[mb][nb][3] = 0.0f;
                }
            }
        }
    }
}

// ---------------------------------------------------------------------------
extern "C" void kernel_launch(void* const* d_in, const int* in_sizes, int n_in,
                              void* d_out, int out_size)
{
    int i_feats = 0, i_protos = 0, i_labels = 0;
    for (int i = 1; i < n_in; i++) {
        if (in_sizes[i] > in_sizes[i_feats])  i_feats  = i;
        if (in_sizes[i] < in_sizes[i_labels]) i_labels = i;
    }
    for (int i = 0; i < n_in; i++)
        if (i != i_feats && i != i_labels) i_protos = i;

    const float* feats  = (const float*)d_in[i_feats];
    const float* protos = (const float*)d_in[i_protos];
    const void*  labels = d_in[i_labels];

    const int N = in_sizes[i_labels];
    const int C = in_sizes[i_protos] / D_DIM;
    float* out = (float*)d_out;

    {
        int total = MAX_C * D_DIM;
        zero_detect<<<(total + 255) / 256, 256>>>((const int*)labels, N);
    }
    normalize_scatter<<<N, 128>>>(feats, labels, C);
    proto_update<<<C, 128>>>(protos);

    static bool smem_set = false;
    if (!smem_set) {
        cudaFuncSetAttribute(gemm_mma, cudaFuncAttributeMaxDynamicSharedMemorySize,
                             SMEM_TOTAL);
        smem_set = true;
    }
    gemm_mma<<<GRID_P, 256, SMEM_TOTAL>>>(out, C);
}

// round 16
// speedup vs baseline: 1.2223x; 1.1435x over previous
#include <cuda_runtime.h>
#include <cuda_fp16.h>
#include <math.h>
#include <stdint.h>

#define D_DIM 512
#define MAX_N 65536
#define MAX_C 1024

// Scratch (allocation-free rule). Referenced ONLY from device code.
__device__ float g_inv[MAX_N];
__device__ float g_sums[MAX_C * D_DIM];
__device__ float g_cnt[MAX_C];
__device__ float g_protos[MAX_C * D_DIM];
__device__ int   g_lab64;
// Precomputed fp16 operands for the tensor-core GEMM
__device__ __half g_Ah[MAX_N * D_DIM];   // 64 MB
__device__ __half g_Bh[MAX_C * D_DIM];   // 1 MB

// ---------------------------------------------------------------------------
__device__ __forceinline__ uint32_t smem_u32(const void* p) {
    uint32_t a;
    asm("{ .reg .u64 t; cvta.to.shared.u64 t, %1; cvt.u32.u64 %0, t; }"
        : "=r"(a) : "l"(p));
    return a;
}
__device__ __forceinline__ uint32_t sw128(uint32_t off) { return off ^ ((off >> 3) & 0x70); }
__device__ __forceinline__ uint32_t h2u(__half2 v) {
    return *reinterpret_cast<uint32_t*>(&v);
}
__device__ __forceinline__ void ldsm_x4(uint32_t& r0, uint32_t& r1, uint32_t& r2,
                                        uint32_t& r3, uint32_t addr) {
    asm volatile("ldmatrix.sync.aligned.m8n8.x4.shared.b16 {%0,%1,%2,%3}, [%4];"
                 : "=r"(r0), "=r"(r1), "=r"(r2), "=r"(r3) : "r"(addr));
}
__device__ __forceinline__ void mma_f16(float* c, const uint32_t* a,
                                        uint32_t b0, uint32_t b1) {
    asm volatile(
        "mma.sync.aligned.m16n8k16.row.col.f32.f16.f16.f32 "
        "{%0,%1,%2,%3}, {%4,%5,%6,%7}, {%8,%9}, {%0,%1,%2,%3};"
        : "+f"(c[0]), "+f"(c[1]), "+f"(c[2]), "+f"(c[3])
        : "r"(a[0]), "r"(a[1]), "r"(a[2]), "r"(a[3]), "r"(b0), "r"(b1));
}
__device__ __forceinline__ void cp16(uint32_t dst, const void* src) {
    asm volatile("cp.async.cg.shared.global [%0], [%1], 16;"
                 :: "r"(dst), "l"(src) : "memory");
}
__device__ __forceinline__ void cp_commit() {
    asm volatile("cp.async.commit_group;" ::: "memory");
}
template <int N>
__device__ __forceinline__ void cp_wait() {
    asm volatile("cp.async.wait_group %0;" :: "n"(N) : "memory");
}
__device__ __forceinline__ void stg_cs_v2(float* p, float x, float y) {
    asm volatile("st.global.cs.v2.f32 [%0], {%1, %2};"
                 :: "l"(p), "f"(x), "f"(y) : "memory");
}

// ===========================================================================
// zero + label-dtype detect (fused)
// ===========================================================================
__global__ void zero_detect(const int* __restrict__ words, int n_words) {
    int i = blockIdx.x * blockDim.x + threadIdx.x;
    if (i < MAX_C * D_DIM) g_sums[i] = 0.0f;
    if (i < MAX_C)         g_cnt[i]  = 0.0f;
    if (i == 0) {
        int all_zero = 1;
        for (int k = 1; k < 256 && k < n_words; k += 2)
            if (words[k] != 0) { all_zero = 0; break; }
        g_lab64 = all_zero;
    }
}

// ===========================================================================
// Per-row L2 norm + segment scatter + emit fp16 of normalized feats.
// ONE WARP PER ROW: lane loads 4 independent float4 (MLP=4), warp-shfl
// reduction only (no smem / no __syncthreads). 8 rows per 256-thread block.
// ===========================================================================
__global__ void __launch_bounds__(256) normalize_scatter(
    const float* __restrict__ feats, const void* __restrict__ labels, int Ccls)
{
    const int warp = threadIdx.x >> 5;
    const int lane = threadIdx.x & 31;
    const int row  = blockIdx.x * 8 + warp;

    const float4* src = reinterpret_cast<const float4*>(feats + (size_t)row * D_DIM);
    // lane j: elements at f4-index lane + 32*j (coalesced per j; 4-way MLP)
    float4 v0 = src[lane];
    float4 v1 = src[lane + 32];
    float4 v2 = src[lane + 64];
    float4 v3 = src[lane + 96];

    float ss = v0.x*v0.x + v0.y*v0.y + v0.z*v0.z + v0.w*v0.w
             + v1.x*v1.x + v1.y*v1.y + v1.z*v1.z + v1.w*v1.w
             + v2.x*v2.x + v2.y*v2.y + v2.z*v2.z + v2.w*v2.w
             + v3.x*v3.x + v3.y*v3.y + v3.z*v3.z + v3.w*v3.w;
    #pragma unroll
    for (int o = 16; o > 0; o >>= 1) ss += __shfl_xor_sync(0xffffffffu, ss, o);
    const float inv = 1.0f / fmaxf(sqrtf(ss), 1e-12f);
    if (lane == 0) g_inv[row] = inv;

    int lab;
    if (lane == 0) {
        if (g_lab64) lab = (int)reinterpret_cast<const long long*>(labels)[row];
        else         lab = reinterpret_cast<const int*>(labels)[row];
        if (lab < 0) lab = 0;
        if (lab >= Ccls) lab = Ccls - 1;
    }
    lab = __shfl_sync(0xffffffffu, lab, 0);

    float* sumrow = g_sums + (size_t)lab * D_DIM;
    uint2* outAh  = reinterpret_cast<uint2*>(g_Ah + (size_t)row * D_DIM);

    float4 vv[4] = {v0, v1, v2, v3};
    #pragma unroll
    for (int j = 0; j < 4; j++) {
        float4 f = make_float4(vv[j].x * inv, vv[j].y * inv,
                               vv[j].z * inv, vv[j].w * inv);
        __half2 a0 = __float22half2_rn(make_float2(f.x, f.y));
        __half2 a1 = __float22half2_rn(make_float2(f.z, f.w));
        outAh[lane + 32 * j] = make_uint2(h2u(a0), h2u(a1));
        asm volatile("red.global.add.v4.f32 [%0], {%1, %2, %3, %4};"
                     :: "l"(sumrow + (lane + 32 * j) * 4),
                        "f"(f.x), "f"(f.y), "f"(f.z), "f"(f.w) : "memory");
    }
    if (lane == 0) atomicAdd(&g_cnt[lab], 1.0f);
}

// ===========================================================================
// Prototype EMA + renorm + emit fp16 of the updated bank
// ===========================================================================
__global__ void __launch_bounds__(128) proto_update(const float* __restrict__ protos)
{
    const int c = blockIdx.x;
    const int t = threadIdx.x;
    const float cnt   = g_cnt[c];
    const float denom = fmaxf(cnt, 1.0f);

    const float4 p = reinterpret_cast<const float4*>(protos + (size_t)c * D_DIM)[t];
    const float4 s = reinterpret_cast<const float4*>(g_sums  + (size_t)c * D_DIM)[t];

    float4 m;
    m.x = 0.9f * p.x + 0.1f * (s.x / denom);
    m.y = 0.9f * p.y + 0.1f * (s.y / denom);
    m.z = 0.9f * p.z + 0.1f * (s.z / denom);
    m.w = 0.9f * p.w + 0.1f * (s.w / denom);

    float ss = m.x * m.x + m.y * m.y + m.z * m.z + m.w * m.w;
    #pragma unroll
    for (int o = 16; o > 0; o >>= 1) ss += __shfl_xor_sync(0xffffffffu, ss, o);
    __shared__ float warp_ss[4];
    if ((t & 31) == 0) warp_ss[t >> 5] = ss;
    __syncthreads();
    const float tot = warp_ss[0] + warp_ss[1] + warp_ss[2] + warp_ss[3];
    const float inv = 1.0f / fmaxf(sqrtf(tot), 1e-12f);

    float4 o4;
    if (cnt > 0.0f) {
        o4.x = m.x * inv; o4.y = m.y * inv; o4.z = m.z * inv; o4.w = m.w * inv;
    } else {
        o4 = p;
    }
    reinterpret_cast<float4*>(g_protos + (size_t)c * D_DIM)[t] = o4;

    __half2 b0 = __float22half2_rn(make_float2(o4.x, o4.y));
    __half2 b1 = __float22half2_rn(make_float2(o4.z, o4.w));
    const size_t e = (size_t)c * D_DIM + t * 4;
    *reinterpret_cast<uint2*>(reinterpret_cast<char*>(g_Bh) + e * 2) =
        make_uint2(h2u(b0), h2u(b1));
}

// ===========================================================================
// GEMM (exact R12 config — proven 165.7us @ tensor 69.1%): block 128x128,
// 256 threads, 8 warps (4x2), warp tile 32x64, 3-stage cp.async, 2 CTAs/SM.
// Plus always-commit tail (removes R12's latent cp.async tail race).
// ===========================================================================
#define GBM 128
#define GBN 128
#define KCH 64
#define NCHUNK (D_DIM / KCH)                 // 8
#define TILE_A 16384                         // 128x64 fp16
#define STAGE_B (2 * TILE_A)                 // A + B = 32KB
#define NSTAGE 3
#define SMEM_TOTAL (NSTAGE * STAGE_B)        // 98304

__global__ void __launch_bounds__(256, 2) gemm_mma(
    float* __restrict__ Cmat, int Ccls)
{
    extern __shared__ char smem[];
    const uint32_t sbase = smem_u32(smem);

    const int tid = threadIdx.x;
    const int wid = tid >> 5, l = tid & 31;
    const int wy = wid >> 1, wx = wid & 1;          // 4x2 warps, 32x64 tiles
    const int bm = blockIdx.y * GBM, bn = blockIdx.x * GBN;

    // ---- cp.async fill mapping ----
    const int q = tid & 7;
    const int r0 = tid >> 3;
    const uint32_t d0 = sw128((uint32_t)(r0 * 128 + q * 16));
    const char* srcA = reinterpret_cast<const char*>(g_Ah)
                     + ((size_t)(bm + r0) * D_DIM + q * 8) * 2;
    const char* srcB = reinterpret_cast<const char*>(g_Bh)
                     + ((size_t)(bn + r0) * D_DIM + q * 8) * 2;

    auto issue_stage = [&](int c) {
        const uint32_t st = sbase + (uint32_t)(c % NSTAGE) * STAGE_B;
        const int koff = c * KCH * 2;
        #pragma unroll
        for (int s = 0; s < 4; s++)
            cp16(st + d0 + s * 4096, srcA + (size_t)s * 32 * (D_DIM * 2) + koff);
        #pragma unroll
        for (int s = 0; s < 4; s++)
            cp16(st + TILE_A + d0 + s * 4096, srcB + (size_t)s * 32 * (D_DIM * 2) + koff);
        cp_commit();
    };

    // ---- ldmatrix lane addressing (validated R5-R15) ----
    const int a_row = (l & 15);
    const int a_kh  = (l >> 4);
    const int b_row = (l & 7) + (l >> 4) * 8;
    const int b_kh  = (l >> 3) & 1;

    float acc[2][8][4];
    #pragma unroll
    for (int m = 0; m < 2; m++)
        #pragma unroll
        for (int n = 0; n < 8; n++)
            #pragma unroll
            for (int i = 0; i < 4; i++) acc[m][n][i] = 0.0f;

    issue_stage(0);
    issue_stage(1);

    for (int c = 0; c < NCHUNK; c++) {
        cp_wait<1>();          // newest = group c+1 -> group c complete
        __syncthreads();
        // always commit one group so wait<1> stays deterministic at the tail
        if (c + 2 < NCHUNK) issue_stage(c + 2);
        else                cp_commit();

        const uint32_t ah_b = sbase + (uint32_t)(c % NSTAGE) * STAGE_B;
        const uint32_t bh_b = ah_b + TILE_A;

        #pragma unroll
        for (int ks = 0; ks < 4; ks++) {
            uint32_t ah[2][4];
            #pragma unroll
            for (int mb = 0; mb < 2; mb++) {
                const uint32_t off = sw128((uint32_t)(
                    (wy * 32 + mb * 16 + a_row) * 128 + ks * 32 + a_kh * 16));
                ldsm_x4(ah[mb][0], ah[mb][1], ah[mb][2], ah[mb][3], ah_b + off);
            }
            #pragma unroll
            for (int nb2 = 0; nb2 < 4; nb2++) {
                uint32_t bh[4];
                const uint32_t off = sw128((uint32_t)(
                    (wx * 64 + nb2 * 16 + b_row) * 128 + ks * 32 + b_kh * 16));
                ldsm_x4(bh[0], bh[1], bh[2], bh[3], bh_b + off);
                #pragma unroll
                for (int mb = 0; mb < 2; mb++)
                    #pragma unroll
                    for (int h = 0; h < 2; h++)
                        mma_f16(acc[mb][nb2 * 2 + h], ah[mb],
                                bh[h * 2], bh[h * 2 + 1]);
            }
        }
    }

    // ---- epilogue (streaming stores) ----
    #pragma unroll
    for (int mb = 0; mb < 2; mb++) {
        const int row = bm + wy * 32 + mb * 16 + (l >> 2);
        #pragma unroll
        for (int nb = 0; nb < 8; nb++) {
            const int col = bn + wx * 64 + nb * 8 + (l & 3) * 2;
            float* o0 = Cmat + (size_t)row * Ccls + col;
            float* o1 = o0 + (size_t)8 * Ccls;
            stg_cs_v2(o0, acc[mb][nb][0], acc[mb][nb][1]);
            stg_cs_v2(o1, acc[mb][nb][2], acc[mb][nb][3]);
        }
    }
}

// ---------------------------------------------------------------------------
extern "C" void kernel_launch(void* const* d_in, const int* in_sizes, int n_in,
                              void* d_out, int out_size)
{
    int i_feats = 0, i_protos = 0, i_labels = 0;
    for (int i = 1; i < n_in; i++) {
        if (in_sizes[i] > in_sizes[i_feats])  i_feats  = i;
        if (in_sizes[i] < in_sizes[i_labels]) i_labels = i;
    }
    for (int i = 0; i < n_in; i++)
        if (i != i_feats && i != i_labels) i_protos = i;

    const float* feats  = (const float*)d_in[i_feats];
    const float* protos = (const float*)d_in[i_protos];
    const void*  labels = d_in[i_labels];

    const int N = in_sizes[i_labels];
    const int C = in_sizes[i_protos] / D_DIM;
    float* out = (float*)d_out;

    {
        int total = MAX_C * D_DIM;
        zero_detect<<<(total + 255) / 256, 256>>>((const int*)labels, N);
    }
    normalize_scatter<<<N / 8, 256>>>(feats, labels, C);
    proto_update<<<C, 128>>>(protos);

    static bool smem_set = false;
    if (!smem_set) {
        cudaFuncSetAttribute(gemm_mma, cudaFuncAttributeMaxDynamicSharedMemorySize,
                             SMEM_TOTAL);
        smem_set = true;
    }
    dim3 grid(C / GBN, N / GBM);   // (8, 512) = 4096 CTAs
    gemm_mma<<<grid, 256, SMEM_TOTAL>>>(out, C);
}

// round 17
// speedup vs baseline: 1.2332x; 1.0089x over previous
#include <cuda_runtime.h>
#include <cuda_fp16.h>
#include <math.h>
#include <stdint.h>

#define D_DIM 512
#define MAX_N 65536
#define MAX_C 1024

// Scratch (allocation-free rule). Referenced ONLY from device code.
// INVARIANT: g_sums / g_cnt are zero at entry to every launch — they start
// zero-initialized and proto_update re-zeroes them at its tail each run.
__device__ float g_inv[MAX_N];
__device__ float g_sums[MAX_C * D_DIM];
__device__ float g_cnt[MAX_C];
__device__ float g_protos[MAX_C * D_DIM];
// Precomputed fp16 operands for the tensor-core GEMM
__device__ __half g_Ah[MAX_N * D_DIM];   // 64 MB
__device__ __half g_Bh[MAX_C * D_DIM];   // 1 MB

// ---------------------------------------------------------------------------
__device__ __forceinline__ uint32_t smem_u32(const void* p) {
    uint32_t a;
    asm("{ .reg .u64 t; cvta.to.shared.u64 t, %1; cvt.u32.u64 %0, t; }"
        : "=r"(a) : "l"(p));
    return a;
}
__device__ __forceinline__ uint32_t sw128(uint32_t off) { return off ^ ((off >> 3) & 0x70); }
__device__ __forceinline__ uint32_t h2u(__half2 v) {
    return *reinterpret_cast<uint32_t*>(&v);
}
__device__ __forceinline__ void ldsm_x4(uint32_t& r0, uint32_t& r1, uint32_t& r2,
                                        uint32_t& r3, uint32_t addr) {
    asm volatile("ldmatrix.sync.aligned.m8n8.x4.shared.b16 {%0,%1,%2,%3}, [%4];"
                 : "=r"(r0), "=r"(r1), "=r"(r2), "=r"(r3) : "r"(addr));
}
__device__ __forceinline__ void mma_f16(float* c, const uint32_t* a,
                                        uint32_t b0, uint32_t b1) {
    asm volatile(
        "mma.sync.aligned.m16n8k16.row.col.f32.f16.f16.f32 "
        "{%0,%1,%2,%3}, {%4,%5,%6,%7}, {%8,%9}, {%0,%1,%2,%3};"
        : "+f"(c[0]), "+f"(c[1]), "+f"(c[2]), "+f"(c[3])
        : "r"(a[0]), "r"(a[1]), "r"(a[2]), "r"(a[3]), "r"(b0), "r"(b1));
}
__device__ __forceinline__ void cp16(uint32_t dst, const void* src) {
    asm volatile("cp.async.cg.shared.global [%0], [%1], 16;"
                 :: "r"(dst), "l"(src) : "memory");
}
__device__ __forceinline__ void cp_commit() {
    asm volatile("cp.async.commit_group;" ::: "memory");
}
template <int N>
__device__ __forceinline__ void cp_wait() {
    asm volatile("cp.async.wait_group %0;" :: "n"(N) : "memory");
}
__device__ __forceinline__ void stg_cs_v2(float* p, float x, float y) {
    asm volatile("st.global.cs.v2.f32 [%0], {%1, %2};"
                 :: "l"(p), "f"(x), "f"(y) : "memory");
}

// ===========================================================================
// Per-row L2 norm + segment scatter + emit fp16 of normalized feats.
// ONE WARP PER ROW, 16 rows / 512 threads per block. Inline label-dtype
// detection (per-warp ballot over the first 32 odd words: all zero <=>
// int64 little-endian with values < 2^31; for int32 labels in [0,1024) the
// false-positive probability is (1/1024)^32 ~ 0).
// ===========================================================================
__global__ void __launch_bounds__(512) normalize_scatter(
    const float* __restrict__ feats, const void* __restrict__ labels, int Ccls)
{
    const int warp = threadIdx.x >> 5;
    const int lane = threadIdx.x & 31;
    const int row  = blockIdx.x * 16 + warp;

    // ---- inline dtype detect (L2-hot after first block) ----
    const int* words = reinterpret_cast<const int*>(labels);
    const int w = words[2 * lane + 1];
    const bool lab64 = (__ballot_sync(0xffffffffu, w == 0) == 0xffffffffu);

    const float4* src = reinterpret_cast<const float4*>(feats + (size_t)row * D_DIM);
    // lane j: elements at f4-index lane + 32*j (coalesced per j; 4-way MLP)
    float4 v0 = src[lane];
    float4 v1 = src[lane + 32];
    float4 v2 = src[lane + 64];
    float4 v3 = src[lane + 96];

    float ss = v0.x*v0.x + v0.y*v0.y + v0.z*v0.z + v0.w*v0.w
             + v1.x*v1.x + v1.y*v1.y + v1.z*v1.z + v1.w*v1.w
             + v2.x*v2.x + v2.y*v2.y + v2.z*v2.z + v2.w*v2.w
             + v3.x*v3.x + v3.y*v3.y + v3.z*v3.z + v3.w*v3.w;
    #pragma unroll
    for (int o = 16; o > 0; o >>= 1) ss += __shfl_xor_sync(0xffffffffu, ss, o);
    const float inv = 1.0f / fmaxf(sqrtf(ss), 1e-12f);
    if (lane == 0) g_inv[row] = inv;

    int lab;
    if (lane == 0) {
        if (lab64) lab = (int)reinterpret_cast<const long long*>(labels)[row];
        else       lab = words[row];
        if (lab < 0) lab = 0;
        if (lab >= Ccls) lab = Ccls - 1;
    }
    lab = __shfl_sync(0xffffffffu, lab, 0);

    float* sumrow = g_sums + (size_t)lab * D_DIM;
    uint2* outAh  = reinterpret_cast<uint2*>(g_Ah + (size_t)row * D_DIM);

    float4 vv[4] = {v0, v1, v2, v3};
    #pragma unroll
    for (int j = 0; j < 4; j++) {
        float4 f = make_float4(vv[j].x * inv, vv[j].y * inv,
                               vv[j].z * inv, vv[j].w * inv);
        __half2 a0 = __float22half2_rn(make_float2(f.x, f.y));
        __half2 a1 = __float22half2_rn(make_float2(f.z, f.w));
        outAh[lane + 32 * j] = make_uint2(h2u(a0), h2u(a1));
        asm volatile("red.global.add.v4.f32 [%0], {%1, %2, %3, %4};"
                     :: "l"(sumrow + (lane + 32 * j) * 4),
                        "f"(f.x), "f"(f.y), "f"(f.z), "f"(f.w) : "memory");
    }
    if (lane == 0) atomicAdd(&g_cnt[lab], 1.0f);
}

// ===========================================================================
// Prototype EMA + renorm + emit fp16 of the updated bank.
// Tail: re-zero g_sums / g_cnt so the next graph replay starts clean
// (replaces the standalone zero kernel).
// ===========================================================================
__global__ void __launch_bounds__(128) proto_update(const float* __restrict__ protos)
{
    const int c = blockIdx.x;
    const int t = threadIdx.x;
    const float cnt   = g_cnt[c];
    const float denom = fmaxf(cnt, 1.0f);

    float4* srow = reinterpret_cast<float4*>(g_sums + (size_t)c * D_DIM) + t;
    const float4 p = reinterpret_cast<const float4*>(protos + (size_t)c * D_DIM)[t];
    const float4 s = *srow;

    float4 m;
    m.x = 0.9f * p.x + 0.1f * (s.x / denom);
    m.y = 0.9f * p.y + 0.1f * (s.y / denom);
    m.z = 0.9f * p.z + 0.1f * (s.z / denom);
    m.w = 0.9f * p.w + 0.1f * (s.w / denom);

    float ss = m.x * m.x + m.y * m.y + m.z * m.z + m.w * m.w;
    #pragma unroll
    for (int o = 16; o > 0; o >>= 1) ss += __shfl_xor_sync(0xffffffffu, ss, o);
    __shared__ float warp_ss[4];
    if ((t & 31) == 0) warp_ss[t >> 5] = ss;
    __syncthreads();
    const float tot = warp_ss[0] + warp_ss[1] + warp_ss[2] + warp_ss[3];
    const float inv = 1.0f / fmaxf(sqrtf(tot), 1e-12f);

    float4 o4;
    if (cnt > 0.0f) {
        o4.x = m.x * inv; o4.y = m.y * inv; o4.z = m.z * inv; o4.w = m.w * inv;
    } else {
        o4 = p;
    }
    reinterpret_cast<float4*>(g_protos + (size_t)c * D_DIM)[t] = o4;

    __half2 b0 = __float22half2_rn(make_float2(o4.x, o4.y));
    __half2 b1 = __float22half2_rn(make_float2(o4.z, o4.w));
    const size_t e = (size_t)c * D_DIM + t * 4;
    *reinterpret_cast<uint2*>(reinterpret_cast<char*>(g_Bh) + e * 2) =
        make_uint2(h2u(b0), h2u(b1));

    // ---- re-zero accumulators for the next replay ----
    // Each thread owns its own g_sums slice (read above, per-thread: no race).
    *srow = make_float4(0.0f, 0.0f, 0.0f, 0.0f);
    // All threads read g_cnt[c] before the __syncthreads above; safe to clear.
    if (t == 0) g_cnt[c] = 0.0f;
}

// ===========================================================================
// GEMM (exact R12/R16 config — proven 163.5us @ tensor 69.4%): block 128x128,
// 256 threads, 8 warps (4x2), warp tile 32x64, 3-stage cp.async, 2 CTAs/SM,
// always-commit tail.
// ===========================================================================
#define GBM 128
#define GBN 128
#define KCH 64
#define NCHUNK (D_DIM / KCH)                 // 8
#define TILE_A 16384                         // 128x64 fp16
#define STAGE_B (2 * TILE_A)                 // A + B = 32KB
#define NSTAGE 3
#define SMEM_TOTAL (NSTAGE * STAGE_B)        // 98304

__global__ void __launch_bounds__(256, 2) gemm_mma(
    float* __restrict__ Cmat, int Ccls)
{
    extern __shared__ char smem[];
    const uint32_t sbase = smem_u32(smem);

    const int tid = threadIdx.x;
    const int wid = tid >> 5, l = tid & 31;
    const int wy = wid >> 1, wx = wid & 1;          // 4x2 warps, 32x64 tiles
    const int bm = blockIdx.y * GBM, bn = blockIdx.x * GBN;

    // ---- cp.async fill mapping ----
    const int q = tid & 7;
    const int r0 = tid >> 3;
    const uint32_t d0 = sw128((uint32_t)(r0 * 128 + q * 16));
    const char* srcA = reinterpret_cast<const char*>(g_Ah)
                     + ((size_t)(bm + r0) * D_DIM + q * 8) * 2;
    const char* srcB = reinterpret_cast<const char*>(g_Bh)
                     + ((size_t)(bn + r0) * D_DIM + q * 8) * 2;

    auto issue_stage = [&](int c) {
        const uint32_t st = sbase + (uint32_t)(c % NSTAGE) * STAGE_B;
        const int koff = c * KCH * 2;
        #pragma unroll
        for (int s = 0; s < 4; s++)
            cp16(st + d0 + s * 4096, srcA + (size_t)s * 32 * (D_DIM * 2) + koff);
        #pragma unroll
        for (int s = 0; s < 4; s++)
            cp16(st + TILE_A + d0 + s * 4096, srcB + (size_t)s * 32 * (D_DIM * 2) + koff);
        cp_commit();
    };

    // ---- ldmatrix lane addressing (validated R5-R16) ----
    const int a_row = (l & 15);
    const int a_kh  = (l >> 4);
    const int b_row = (l & 7) + (l >> 4) * 8;
    const int b_kh  = (l >> 3) & 1;

    float acc[2][8][4];
    #pragma unroll
    for (int m = 0; m < 2; m++)
        #pragma unroll
        for (int n = 0; n < 8; n++)
            #pragma unroll
            for (int i = 0; i < 4; i++) acc[m][n][i] = 0.0f;

    issue_stage(0);
    issue_stage(1);

    for (int c = 0; c < NCHUNK; c++) {
        cp_wait<1>();          // newest = group c+1 -> group c complete
        __syncthreads();
        // always commit one group so wait<1> stays deterministic at the tail
        if (c + 2 < NCHUNK) issue_stage(c + 2);
        else                cp_commit();

        const uint32_t ah_b = sbase + (uint32_t)(c % NSTAGE) * STAGE_B;
        const uint32_t bh_b = ah_b + TILE_A;

        #pragma unroll
        for (int ks = 0; ks < 4; ks++) {
            uint32_t ah[2][4];
            #pragma unroll
            for (int mb = 0; mb < 2; mb++) {
                const uint32_t off = sw128((uint32_t)(
                    (wy * 32 + mb * 16 + a_row) * 128 + ks * 32 + a_kh * 16));
                ldsm_x4(ah[mb][0], ah[mb][1], ah[mb][2], ah[mb][3], ah_b + off);
            }
            #pragma unroll
            for (int nb2 = 0; nb2 < 4; nb2++) {
                uint32_t bh[4];
                const uint32_t off = sw128((uint32_t)(
                    (wx * 64 + nb2 * 16 + b_row) * 128 + ks * 32 + b_kh * 16));
                ldsm_x4(bh[0], bh[1], bh[2], bh[3], bh_b + off);
                #pragma unroll
                for (int mb = 0; mb < 2; mb++)
                    #pragma unroll
                    for (int h = 0; h < 2; h++)
                        mma_f16(acc[mb][nb2 * 2 + h], ah[mb],
                                bh[h * 2], bh[h * 2 + 1]);
            }
        }
    }

    // ---- epilogue (streaming stores) ----
    #pragma unroll
    for (int mb = 0; mb < 2; mb++) {
        const int row = bm + wy * 32 + mb * 16 + (l >> 2);
        #pragma unroll
        for (int nb = 0; nb < 8; nb++) {
            const int col = bn + wx * 64 + nb * 8 + (l & 3) * 2;
            float* o0 = Cmat + (size_t)row * Ccls + col;
            float* o1 = o0 + (size_t)8 * Ccls;
            stg_cs_v2(o0, acc[mb][nb][0], acc[mb][nb][1]);
            stg_cs_v2(o1, acc[mb][nb][2], acc[mb][nb][3]);
        }
    }
}

// ---------------------------------------------------------------------------
extern "C" void kernel_launch(void* const* d_in, const int* in_sizes, int n_in,
                              void* d_out, int out_size)
{
    int i_feats = 0, i_protos = 0, i_labels = 0;
    for (int i = 1; i < n_in; i++) {
        if (in_sizes[i] > in_sizes[i_feats])  i_feats  = i;
        if (in_sizes[i] < in_sizes[i_labels]) i_labels = i;
    }
    for (int i = 0; i < n_in; i++)
        if (i != i_feats && i != i_labels) i_protos = i;

    const float* feats  = (const float*)d_in[i_feats];
    const float* protos = (const float*)d_in[i_protos];
    const void*  labels = d_in[i_labels];

    const int N = in_sizes[i_labels];
    const int C = in_sizes[i_protos] / D_DIM;
    float* out = (float*)d_out;

    normalize_scatter<<<N / 16, 512>>>(feats, labels, C);
    proto_update<<<C, 128>>>(protos);

    static bool smem_set = false;
    if (!smem_set) {
        cudaFuncSetAttribute(gemm_mma, cudaFuncAttributeMaxDynamicSharedMemorySize,
                             SMEM_TOTAL);
        smem_set = true;
    }
    dim3 grid(C / GBN, N / GBM);   // (8, 512) = 4096 CTAs
    gemm_mma<<<grid, 256, SMEM_TOTAL>>>(out, C);
}